// round 1
// baseline (speedup 1.0000x reference)
#include <cuda_runtime.h>
#include <math.h>

// Problem constants
#define TOKENS 4096      // b*l
#define BATCH  4
#define LSEQ   1024
#define DMODEL 1024
#define DI     2048
#define NSTATE 16
#define DTR    64
#define XDBL_W 96        // dtr + 2n

// -------- scratch (device globals; no allocation allowed) --------
__device__ float g_h[TOKENS * DMODEL];       // residual stream
__device__ float g_xn[TOKENS * DMODEL];      // rmsnorm output
__device__ float g_xr[TOKENS * (2 * DI)];    // in_proj output (xs | res)
__device__ float g_xs[TOKENS * DI];          // conv+silu output
__device__ float g_xdbl[TOKENS * XDBL_W];    // x_proj output (dlt|B|C)
__device__ float g_delta[TOKENS * DI];       // softplus(dt_proj)
__device__ float g_y[TOKENS * DI];           // scan output * silu(res)

__device__ __forceinline__ float softplusf(float x) {
    return (x > 20.0f) ? x : log1pf(__expf(x));
}
__device__ __forceinline__ float siluf(float x) {
    return x / (1.0f + __expf(-x));
}

// -------- copy x -> g_h --------
__global__ void __launch_bounds__(256) copy_kernel(const float* __restrict__ src,
                                                   float* __restrict__ dst, int n4) {
    int i = blockIdx.x * 256 + threadIdx.x;
    if (i < n4) ((float4*)dst)[i] = ((const float4*)src)[i];
}

// -------- rmsnorm: one block per token row of 1024 --------
__global__ void __launch_bounds__(256) rmsnorm_kernel(const float* __restrict__ src,
                                                      const float* __restrict__ w,
                                                      float* __restrict__ dst) {
    int row = blockIdx.x;
    const float4* s = (const float4*)(src + (size_t)row * DMODEL);
    float4 v = s[threadIdx.x];
    float ss = v.x * v.x + v.y * v.y + v.z * v.z + v.w * v.w;
    #pragma unroll
    for (int o = 16; o; o >>= 1) ss += __shfl_xor_sync(0xffffffffu, ss, o);
    __shared__ float wsum[8];
    if ((threadIdx.x & 31) == 0) wsum[threadIdx.x >> 5] = ss;
    __syncthreads();
    float tot = 0.f;
    #pragma unroll
    for (int i = 0; i < 8; i++) tot += wsum[i];
    float rs = rsqrtf(tot * (1.0f / DMODEL) + 1e-5f);
    float4 wv = ((const float4*)w)[threadIdx.x];
    float4 o;
    o.x = v.x * rs * wv.x; o.y = v.y * rs * wv.y;
    o.z = v.z * rs * wv.z; o.w = v.w * rs * wv.w;
    ((float4*)(dst + (size_t)row * DMODEL))[threadIdx.x] = o;
}

// -------- generic NT GEMM: C[M,N] = A[M,K] * B[N,K]^T (+ epilogue) --------
// EPI: 0 = +bias (bias may be null), 1 = softplus(+bias), 2 = C += acc + bias
#define GBM 128
#define GBN 128
#define GBK 16

template <int EPI>
__global__ void __launch_bounds__(256) gemm_nt(
    const float* __restrict__ A, int lda,
    const float* __restrict__ Bm, int ldb,
    const float* __restrict__ bias,
    float* __restrict__ C, int ldc,
    int M, int N, int K) {
    __shared__ float As[2][GBK][GBM];
    __shared__ float Bs[2][GBK][GBN];
    const int tid = threadIdx.x;
    const int bm = blockIdx.y * GBM;
    const int bn = blockIdx.x * GBN;
    const int ty = tid >> 4;       // 0..15
    const int tx = tid & 15;       // 0..15
    const int lr0 = tid >> 2;      // 0..63
    const int lc = (tid & 3) * 4;  // 0,4,8,12

    float acc[8][8];
    #pragma unroll
    for (int i = 0; i < 8; i++)
        #pragma unroll
        for (int j = 0; j < 8; j++) acc[i][j] = 0.f;

    const int nk = K / GBK;  // all K here are multiples of 16
    float4 ra[2], rb[2];

    // prologue: tile 0
    #pragma unroll
    for (int hh = 0; hh < 2; hh++) {
        int r = lr0 + hh * 64;
        ra[hh] = *(const float4*)(A + (size_t)(bm + r) * lda + lc);
        int jr = bn + r;
        rb[hh] = (jr < N) ? *(const float4*)(Bm + (size_t)jr * ldb + lc)
                          : make_float4(0.f, 0.f, 0.f, 0.f);
    }
    #pragma unroll
    for (int hh = 0; hh < 2; hh++) {
        int r = lr0 + hh * 64;
        As[0][lc + 0][r] = ra[hh].x; As[0][lc + 1][r] = ra[hh].y;
        As[0][lc + 2][r] = ra[hh].z; As[0][lc + 3][r] = ra[hh].w;
        Bs[0][lc + 0][r] = rb[hh].x; Bs[0][lc + 1][r] = rb[hh].y;
        Bs[0][lc + 2][r] = rb[hh].z; Bs[0][lc + 3][r] = rb[hh].w;
    }
    __syncthreads();

    for (int kt = 0; kt < nk; kt++) {
        int cur = kt & 1;
        if (kt + 1 < nk) {
            int k0 = (kt + 1) * GBK;
            #pragma unroll
            for (int hh = 0; hh < 2; hh++) {
                int r = lr0 + hh * 64;
                ra[hh] = *(const float4*)(A + (size_t)(bm + r) * lda + k0 + lc);
                int jr = bn + r;
                rb[hh] = (jr < N) ? *(const float4*)(Bm + (size_t)jr * ldb + k0 + lc)
                                  : make_float4(0.f, 0.f, 0.f, 0.f);
            }
        }
        #pragma unroll
        for (int kk = 0; kk < GBK; kk++) {
            float a[8], b[8];
            *(float4*)&a[0] = *(const float4*)&As[cur][kk][ty * 8];
            *(float4*)&a[4] = *(const float4*)&As[cur][kk][ty * 8 + 4];
            *(float4*)&b[0] = *(const float4*)&Bs[cur][kk][tx * 8];
            *(float4*)&b[4] = *(const float4*)&Bs[cur][kk][tx * 8 + 4];
            #pragma unroll
            for (int i = 0; i < 8; i++)
                #pragma unroll
                for (int j = 0; j < 8; j++)
                    acc[i][j] = fmaf(a[i], b[j], acc[i][j]);
        }
        if (kt + 1 < nk) {
            int nb = cur ^ 1;
            #pragma unroll
            for (int hh = 0; hh < 2; hh++) {
                int r = lr0 + hh * 64;
                As[nb][lc + 0][r] = ra[hh].x; As[nb][lc + 1][r] = ra[hh].y;
                As[nb][lc + 2][r] = ra[hh].z; As[nb][lc + 3][r] = ra[hh].w;
                Bs[nb][lc + 0][r] = rb[hh].x; Bs[nb][lc + 1][r] = rb[hh].y;
                Bs[nb][lc + 2][r] = rb[hh].z; Bs[nb][lc + 3][r] = rb[hh].w;
            }
        }
        __syncthreads();
    }

    // epilogue (M always multiple of 128 here; only N needs guarding)
    #pragma unroll
    for (int i = 0; i < 8; i++) {
        int m = bm + ty * 8 + i;
        #pragma unroll
        for (int j = 0; j < 8; j++) {
            int n = bn + tx * 8 + j;
            if (n < N) {
                float v = acc[i][j];
                if (bias) v += bias[n];
                if (EPI == 1) v = softplusf(v);
                if (EPI == 2) v += C[(size_t)m * ldc + n];
                C[(size_t)m * ldc + n] = v;
            }
        }
    }
}

// -------- depthwise conv1d (k=5, symmetric pad 2, cross-correlation) + silu --------
__global__ void __launch_bounds__(256) conv_silu_kernel(
    const float* __restrict__ xr, const float* __restrict__ cw,
    const float* __restrict__ cb, float* __restrict__ xs) {
    int idx = blockIdx.x * 256 + threadIdx.x;  // over TOKENS*DI
    int c = idx & (DI - 1);
    int tok = idx >> 11;
    int t = tok & (LSEQ - 1);
    int b = tok >> 10;
    const float* base = xr + (size_t)(b * LSEQ) * (2 * DI) + c;
    float acc = cb[c];
    #pragma unroll
    for (int j = 0; j < 5; j++) {
        int tt = t + j - 2;
        if (tt >= 0 && tt < LSEQ)
            acc = fmaf(base[(size_t)tt * (2 * DI)], __ldg(cw + c * 5 + j), acc);
    }
    xs[idx] = siluf(acc);
}

// -------- selective scan: 16 lanes per (b,d) channel, one lane per n --------
__global__ void __launch_bounds__(256) scan_kernel(
    const float* __restrict__ delta, const float* __restrict__ u,
    const float* __restrict__ xdbl, const float* __restrict__ A_log,
    const float* __restrict__ Dv, const float* __restrict__ xr,
    float* __restrict__ y) {
    int gid = blockIdx.x * 256 + threadIdx.x;
    int n = gid & 15;
    int hw = gid >> 4;        // channel 0..8191
    int d = hw & (DI - 1);
    int b = hw >> 11;
    float A = -__expf(A_log[d * NSTATE + n]);
    float Dd = Dv[d];
    float h = 0.f;
    const float* dptr = delta + (size_t)(b * LSEQ) * DI + d;
    const float* uptr = u + (size_t)(b * LSEQ) * DI + d;
    const float* xptr = xdbl + (size_t)(b * LSEQ) * XDBL_W;
    const float* rptr = xr + (size_t)(b * LSEQ) * (2 * DI) + DI + d;
    float* yptr = y + (size_t)(b * LSEQ) * DI + d;
    #pragma unroll 4
    for (int t = 0; t < LSEQ; t++) {
        float dlt = dptr[(size_t)t * DI];
        float uu = uptr[(size_t)t * DI];
        float Bn = xptr[t * XDBL_W + DTR + n];
        float Cn = xptr[t * XDBL_W + DTR + NSTATE + n];
        float dA = __expf(dlt * A);
        h = fmaf(dA, h, dlt * uu * Bn);
        float v = h * Cn;
        v += __shfl_xor_sync(0xffffffffu, v, 8);
        v += __shfl_xor_sync(0xffffffffu, v, 4);
        v += __shfl_xor_sync(0xffffffffu, v, 2);
        v += __shfl_xor_sync(0xffffffffu, v, 1);
        if (n == 0) {
            float r = rptr[(size_t)t * (2 * DI)];
            yptr[(size_t)t * DI] = (v + uu * Dd) * siluf(r);
        }
    }
}

extern "C" void kernel_launch(void* const* d_in, const int* in_sizes, int n_in,
                              void* d_out, int out_size) {
    const float* x      = (const float*)d_in[0];
    const float* Wi     = (const float*)d_in[1];
    const float* bi     = (const float*)d_in[2];
    const float* cw     = (const float*)d_in[3];
    const float* cb     = (const float*)d_in[4];
    const float* Wx     = (const float*)d_in[5];
    const float* Wdt    = (const float*)d_in[6];
    const float* bdt    = (const float*)d_in[7];
    const float* A_log  = (const float*)d_in[8];
    const float* Dv     = (const float*)d_in[9];
    const float* Wo     = (const float*)d_in[10];
    const float* bo     = (const float*)d_in[11];
    const float* norm_w = (const float*)d_in[12];
    const float* nfw    = (const float*)d_in[13];
    float* out = (float*)d_out;

    float *hb, *xn, *xr, *xs, *xdbl, *delta, *yb;
    cudaGetSymbolAddress((void**)&hb, g_h);
    cudaGetSymbolAddress((void**)&xn, g_xn);
    cudaGetSymbolAddress((void**)&xr, g_xr);
    cudaGetSymbolAddress((void**)&xs, g_xs);
    cudaGetSymbolAddress((void**)&xdbl, g_xdbl);
    cudaGetSymbolAddress((void**)&delta, g_delta);
    cudaGetSymbolAddress((void**)&yb, g_y);

    // h = x
    copy_kernel<<<(TOKENS * DMODEL / 4) / 256, 256>>>(x, hb, TOKENS * DMODEL / 4);

    for (int i = 0; i < 2; i++) {
        const float* Wi_l  = Wi + (size_t)i * (2 * DI) * DMODEL;
        const float* bi_l  = bi + (size_t)i * (2 * DI);
        const float* cw_l  = cw + (size_t)i * DI * 5;
        const float* cb_l  = cb + (size_t)i * DI;
        const float* Wx_l  = Wx + (size_t)i * XDBL_W * DI;
        const float* Wdt_l = Wdt + (size_t)i * DI * DTR;
        const float* bdt_l = bdt + (size_t)i * DI;
        const float* Al_l  = A_log + (size_t)i * DI * NSTATE;
        const float* D_l   = Dv + (size_t)i * DI;
        const float* Wo_l  = Wo + (size_t)i * DMODEL * DI;
        const float* bo_l  = bo + (size_t)i * DMODEL;
        const float* nw_l  = norm_w + (size_t)i * DMODEL;

        // xn = rmsnorm(h, norm_w)
        rmsnorm_kernel<<<TOKENS, 256>>>(hb, nw_l, xn);

        // xr = xn @ Wi^T + bi   [4096, 4096]
        {
            dim3 g((2 * DI) / GBN, TOKENS / GBM);
            gemm_nt<0><<<g, 256>>>(xn, DMODEL, Wi_l, DMODEL, bi_l, xr, 2 * DI,
                                   TOKENS, 2 * DI, DMODEL);
        }

        // xs = silu(depthwise_conv(xr[:, :2048]) + cb)
        conv_silu_kernel<<<(TOKENS * DI) / 256, 256>>>(xr, cw_l, cb_l, xs);

        // xdbl = xs @ Wx^T   [4096, 96]
        {
            dim3 g((XDBL_W + GBN - 1) / GBN, TOKENS / GBM);
            gemm_nt<0><<<g, 256>>>(xs, DI, Wx_l, DI, nullptr, xdbl, XDBL_W,
                                   TOKENS, XDBL_W, DI);
        }

        // delta = softplus(xdbl[:, :64] @ Wdt^T + bdt)   [4096, 2048]
        {
            dim3 g(DI / GBN, TOKENS / GBM);
            gemm_nt<1><<<g, 256>>>(xdbl, XDBL_W, Wdt_l, DTR, bdt_l, delta, DI,
                                   TOKENS, DI, DTR);
        }

        // y = (selective_scan(xs, delta, A, B, C, D)) * silu(res)
        scan_kernel<<<(BATCH * DI * NSTATE) / 256, 256>>>(delta, xs, xdbl, Al_l,
                                                          D_l, xr, yb);

        // h += y @ Wo^T + bo
        {
            dim3 g(DMODEL / GBN, TOKENS / GBM);
            gemm_nt<2><<<g, 256>>>(yb, DI, Wo_l, DI, bo_l, hb, DMODEL,
                                   TOKENS, DMODEL, DI);
        }
    }

    // out = rmsnorm(h, norm_f_w)
    rmsnorm_kernel<<<TOKENS, 256>>>(hb, nfw, out);
}

// round 3
// speedup vs baseline: 1.7770x; 1.7770x over previous
#include <cuda_runtime.h>
#include <math.h>
#include <cstdint>

#define TOKENS 4096
#define BATCH  4
#define LSEQ   1024
#define DMODEL 1024
#define DI     2048
#define NSTATE 16
#define DTR    64
#define XDBL_W 96

// ---------------- helpers ----------------
__device__ __forceinline__ uint32_t smem_to_u32(const void* p) {
    uint32_t a;
    asm("{ .reg .u64 t; cvta.to.shared.u64 t, %1; cvt.u32.u64 %0, t; }" : "=r"(a) : "l"(p));
    return a;
}
__device__ __forceinline__ void cp16(uint32_t dst, const float* src, uint32_t nbytes) {
    asm volatile("cp.async.cg.shared.global [%0], [%1], 16, %2;"
                 :: "r"(dst), "l"(src), "r"(nbytes) : "memory");
}
__device__ __forceinline__ float tf32r(float x) {
    uint32_t u; asm("cvt.rna.tf32.f32 %0, %1;" : "=r"(u) : "f"(x));
    return __uint_as_float(u);
}
__device__ __forceinline__ float softplusf(float x) {
    return (x > 20.0f) ? x : log1pf(__expf(x));
}
__device__ __forceinline__ float siluf(float x) { return x / (1.0f + __expf(-x)); }

#define MMA_TF32(c, a, b) \
    asm volatile("mma.sync.aligned.m16n8k8.row.col.f32.tf32.tf32.f32 " \
        "{%0,%1,%2,%3}, {%4,%5,%6,%7}, {%8,%9}, {%0,%1,%2,%3};" \
        : "+f"((c)[0]), "+f"((c)[1]), "+f"((c)[2]), "+f"((c)[3]) \
        : "r"((a)[0]), "r"((a)[1]), "r"((a)[2]), "r"((a)[3]), \
          "r"((b)[0]), "r"((b)[1]))

// ---------------- scratch (device globals) ----------------
__device__ __align__(256) float g_h[TOKENS * DMODEL];
__device__ __align__(256) float g_xn[TOKENS * DMODEL];
__device__ __align__(256) float g_xr[TOKENS * (2 * DI)];
__device__ __align__(256) float g_xs[TOKENS * DI];
__device__ __align__(256) float g_xdbl[TOKENS * XDBL_W];
__device__ __align__(256) float g_delta[TOKENS * DI];
__device__ __align__(256) float g_y[TOKENS * DI];
__device__ __align__(256) float g_wi[(2 * DI) * DMODEL];
__device__ __align__(256) float g_wo[DMODEL * DI];
__device__ __align__(256) float g_wx[XDBL_W * DI];
__device__ __align__(256) float g_wdt[DI * DTR];

// ---------------- elementwise kernels ----------------
__global__ void __launch_bounds__(256) copy_kernel(const float* __restrict__ src,
                                                   float* __restrict__ dst, int n4) {
    int i = blockIdx.x * 256 + threadIdx.x;
    if (i < n4) ((float4*)dst)[i] = ((const float4*)src)[i];
}

__global__ void __launch_bounds__(256) round_tf32_kernel(const float* __restrict__ src,
                                                         float* __restrict__ dst, int n4) {
    int i = blockIdx.x * 256 + threadIdx.x;
    if (i < n4) {
        float4 v = ((const float4*)src)[i];
        v.x = tf32r(v.x); v.y = tf32r(v.y); v.z = tf32r(v.z); v.w = tf32r(v.w);
        ((float4*)dst)[i] = v;
    }
}

__global__ void __launch_bounds__(256) rmsnorm_kernel(const float* __restrict__ src,
                                                      const float* __restrict__ w,
                                                      float* __restrict__ dst, int round_out) {
    int row = blockIdx.x;
    const float4* s = (const float4*)(src + (size_t)row * DMODEL);
    float4 v = s[threadIdx.x];
    float ss = v.x * v.x + v.y * v.y + v.z * v.z + v.w * v.w;
    #pragma unroll
    for (int o = 16; o; o >>= 1) ss += __shfl_xor_sync(0xffffffffu, ss, o);
    __shared__ float wsum[8];
    if ((threadIdx.x & 31) == 0) wsum[threadIdx.x >> 5] = ss;
    __syncthreads();
    float tot = 0.f;
    #pragma unroll
    for (int i = 0; i < 8; i++) tot += wsum[i];
    float rs = rsqrtf(tot * (1.0f / DMODEL) + 1e-5f);
    float4 wv = ((const float4*)w)[threadIdx.x];
    float4 o;
    o.x = v.x * rs * wv.x; o.y = v.y * rs * wv.y;
    o.z = v.z * rs * wv.z; o.w = v.w * rs * wv.w;
    if (round_out) { o.x = tf32r(o.x); o.y = tf32r(o.y); o.z = tf32r(o.z); o.w = tf32r(o.w); }
    ((float4*)(dst + (size_t)row * DMODEL))[threadIdx.x] = o;
}

__global__ void __launch_bounds__(256) conv_silu_kernel(
    const float* __restrict__ xr, const float* __restrict__ cw,
    const float* __restrict__ cb, float* __restrict__ xs) {
    int idx = blockIdx.x * 256 + threadIdx.x;
    int c = idx & (DI - 1);
    int tok = idx >> 11;
    int t = tok & (LSEQ - 1);
    int b = tok >> 10;
    const float* base = xr + (size_t)(b * LSEQ) * (2 * DI) + c;
    float acc = cb[c];
    #pragma unroll
    for (int j = 0; j < 5; j++) {
        int tt = t + j - 2;
        if (tt >= 0 && tt < LSEQ)
            acc = fmaf(base[(size_t)tt * (2 * DI)], __ldg(cw + c * 5 + j), acc);
    }
    xs[idx] = tf32r(siluf(acc));
}

__global__ void __launch_bounds__(256) scan_kernel(
    const float* __restrict__ delta, const float* __restrict__ u,
    const float* __restrict__ xdbl, const float* __restrict__ A_log,
    const float* __restrict__ Dv, const float* __restrict__ xr,
    float* __restrict__ y) {
    int gid = blockIdx.x * 256 + threadIdx.x;
    int n = gid & 15;
    int hw = gid >> 4;
    int d = hw & (DI - 1);
    int b = hw >> 11;
    float A = -__expf(A_log[d * NSTATE + n]);
    float Dd = Dv[d];
    float h = 0.f;
    const float* dptr = delta + (size_t)(b * LSEQ) * DI + d;
    const float* uptr = u + (size_t)(b * LSEQ) * DI + d;
    const float* xptr = xdbl + (size_t)(b * LSEQ) * XDBL_W;
    const float* rptr = xr + (size_t)(b * LSEQ) * (2 * DI) + DI + d;
    float* yptr = y + (size_t)(b * LSEQ) * DI + d;
    #pragma unroll 4
    for (int t = 0; t < LSEQ; t++) {
        float dlt = dptr[(size_t)t * DI];
        float uu = uptr[(size_t)t * DI];
        float Bn = xptr[t * XDBL_W + DTR + n];
        float Cn = xptr[t * XDBL_W + DTR + NSTATE + n];
        float dA = __expf(dlt * A);
        h = fmaf(dA, h, dlt * uu * Bn);
        float v = h * Cn;
        v += __shfl_xor_sync(0xffffffffu, v, 8);
        v += __shfl_xor_sync(0xffffffffu, v, 4);
        v += __shfl_xor_sync(0xffffffffu, v, 2);
        v += __shfl_xor_sync(0xffffffffu, v, 1);
        if (n == 0) {
            float r = rptr[(size_t)t * (2 * DI)];
            yptr[(size_t)t * DI] = tf32r((v + uu * Dd) * siluf(r));
        }
    }
}

// ---------------- tf32 mma.sync GEMM ----------------
// C[M,N] = A[M,K] @ B[N,K]^T (+ epilogue). BM=BN=128, BK=16, 8 warps (warp 64x32).
// EPI: 0 = (+bias), 1 = softplus(+bias), 2 = C += acc + bias
#define GBK 16
#define NSTG 4
#define ASTR 20                    // padded floats per smem row (conflict-free)
#define STAGE_FLOATS (2 * 128 * ASTR)   // As + Bs = 5120 floats
#define STAGE_BYTES  (STAGE_FLOATS * 4) // 20480
#define GEMM_SMEM    (NSTG * STAGE_BYTES)

template <int EPI, int ROUND>
__global__ void __launch_bounds__(256) gemm_mma(
    const float* __restrict__ A, int lda,
    const float* __restrict__ B, int ldb,
    const float* __restrict__ bias,
    float* __restrict__ C, int ldc,
    int N, int K) {
    extern __shared__ float sm[];
    const uint32_t sbase = smem_to_u32(sm);
    const int tid = threadIdx.x;
    const int lane = tid & 31;
    const int wid = tid >> 5;
    const int wm = (wid >> 2) * 64;   // warp M offset
    const int wn = (wid & 3) * 32;    // warp N offset
    const int bm = blockIdx.y * 128;
    const int bn = blockIdx.x * 128;
    const int NK = K / GBK;

    // per-thread global->smem coords: 512 chunks of 16B per matrix per stage
    const int row1 = tid >> 2;        // 0..63 (also +64)
    const int kp = tid & 3;           // 16B chunk within row
    const uint32_t dA1 = row1 * (ASTR * 4) + kp * 16;
    const uint32_t dA2 = dA1 + 64 * (ASTR * 4);
    const uint32_t dB = 128 * ASTR * 4;  // Bs offset within stage

    const float* aRow1 = A + (size_t)(bm + row1) * lda + kp * 4;
    const float* aRow2 = aRow1 + (size_t)64 * lda;
    const int brow1 = bn + row1, brow2 = bn + row1 + 64;
    const uint32_t nb1 = (brow1 < N) ? 16u : 0u;
    const uint32_t nb2 = (brow2 < N) ? 16u : 0u;
    const float* bRow1 = B + (size_t)(brow1 < N ? brow1 : 0) * ldb + kp * 4;
    const float* bRow2 = B + (size_t)(brow2 < N ? brow2 : 0) * ldb + kp * 4;

    // prologue: issue 3 stages (all shapes have NK >= 4)
    #pragma unroll
    for (int s = 0; s < NSTG - 1; s++) {
        uint32_t st = sbase + s * STAGE_BYTES;
        int k0 = s * GBK;
        cp16(st + dA1, aRow1 + k0, 16);
        cp16(st + dA2, aRow2 + k0, 16);
        cp16(st + dB + dA1, bRow1 + k0, nb1);
        cp16(st + dB + dA2, bRow2 + k0, nb2);
        asm volatile("cp.async.commit_group;" ::: "memory");
    }

    float acc[4][4][4];
    #pragma unroll
    for (int mt = 0; mt < 4; mt++)
        #pragma unroll
        for (int nt = 0; nt < 4; nt++)
            #pragma unroll
            for (int r = 0; r < 4; r++) acc[mt][nt][r] = 0.f;

    const int fr = lane >> 2;   // fragment row within 8
    const int fc = lane & 3;    // fragment k within 4

    for (int kt = 0; kt < NK; kt++) {
        asm volatile("cp.async.wait_group %0;" :: "n"(NSTG - 2));
        __syncthreads();

        // issue stage kt+3 (overwrites buffer computed at kt-1; sync above guards it)
        if (kt + NSTG - 1 < NK) {
            uint32_t st = sbase + ((kt + NSTG - 1) & (NSTG - 1)) * STAGE_BYTES;
            int k0 = (kt + NSTG - 1) * GBK;
            cp16(st + dA1, aRow1 + k0, 16);
            cp16(st + dA2, aRow2 + k0, 16);
            cp16(st + dB + dA1, bRow1 + k0, nb1);
            cp16(st + dB + dA2, bRow2 + k0, nb2);
        }
        asm volatile("cp.async.commit_group;" ::: "memory");

        const float* As = sm + (kt & (NSTG - 1)) * STAGE_FLOATS;
        const float* Bs = As + 128 * ASTR;

        #pragma unroll
        for (int ks = 0; ks < 2; ks++) {
            const int k0 = ks * 8 + fc;
            uint32_t a[4][4], b[4][2];
            #pragma unroll
            for (int mt = 0; mt < 4; mt++) {
                const float* ap = As + (wm + mt * 16 + fr) * ASTR;
                a[mt][0] = __float_as_uint(ap[k0]);
                a[mt][1] = __float_as_uint(ap[8 * ASTR + k0]);
                a[mt][2] = __float_as_uint(ap[k0 + 4]);
                a[mt][3] = __float_as_uint(ap[8 * ASTR + k0 + 4]);
            }
            #pragma unroll
            for (int nt = 0; nt < 4; nt++) {
                const float* bp = Bs + (wn + nt * 8 + fr) * ASTR;
                b[nt][0] = __float_as_uint(bp[k0]);
                b[nt][1] = __float_as_uint(bp[k0 + 4]);
            }
            #pragma unroll
            for (int mt = 0; mt < 4; mt++)
                #pragma unroll
                for (int nt = 0; nt < 4; nt++)
                    MMA_TF32(acc[mt][nt], a[mt], b[nt]);
        }
        __syncthreads();
    }

    // epilogue
    #pragma unroll
    for (int mt = 0; mt < 4; mt++) {
        const int row = bm + wm + mt * 16 + fr;
        #pragma unroll
        for (int nt = 0; nt < 4; nt++) {
            const int col = bn + wn + nt * 8 + 2 * fc;
            if (col < N) {
                #pragma unroll
                for (int half = 0; half < 2; half++) {
                    const int r = row + half * 8;
                    float2 v;
                    v.x = acc[mt][nt][half * 2];
                    v.y = acc[mt][nt][half * 2 + 1];
                    if (bias) { v.x += bias[col]; v.y += bias[col + 1]; }
                    if (EPI == 1) { v.x = softplusf(v.x); v.y = softplusf(v.y); }
                    if (EPI == 2) {
                        float2 o = *(const float2*)(C + (size_t)r * ldc + col);
                        v.x += o.x; v.y += o.y;
                    }
                    if (ROUND) { v.x = tf32r(v.x); v.y = tf32r(v.y); }
                    *(float2*)(C + (size_t)r * ldc + col) = v;
                }
            }
        }
    }
}

// ---------------- host ----------------
extern "C" void kernel_launch(void* const* d_in, const int* in_sizes, int n_in,
                              void* d_out, int out_size) {
    const float* x      = (const float*)d_in[0];
    const float* Wi     = (const float*)d_in[1];
    const float* bi     = (const float*)d_in[2];
    const float* cw     = (const float*)d_in[3];
    const float* cb     = (const float*)d_in[4];
    const float* Wx     = (const float*)d_in[5];
    const float* Wdt    = (const float*)d_in[6];
    const float* bdt    = (const float*)d_in[7];
    const float* A_log  = (const float*)d_in[8];
    const float* Dv     = (const float*)d_in[9];
    const float* Wo     = (const float*)d_in[10];
    const float* bo     = (const float*)d_in[11];
    const float* norm_w = (const float*)d_in[12];
    const float* nfw    = (const float*)d_in[13];
    float* out = (float*)d_out;

    cudaFuncSetAttribute(gemm_mma<0, 0>, cudaFuncAttributeMaxDynamicSharedMemorySize, GEMM_SMEM);
    cudaFuncSetAttribute(gemm_mma<0, 1>, cudaFuncAttributeMaxDynamicSharedMemorySize, GEMM_SMEM);
    cudaFuncSetAttribute(gemm_mma<1, 0>, cudaFuncAttributeMaxDynamicSharedMemorySize, GEMM_SMEM);
    cudaFuncSetAttribute(gemm_mma<2, 0>, cudaFuncAttributeMaxDynamicSharedMemorySize, GEMM_SMEM);

    float *hb, *xn, *xr, *xs, *xdbl, *delta, *yb, *wi, *wo, *wx, *wdt;
    cudaGetSymbolAddress((void**)&hb, g_h);
    cudaGetSymbolAddress((void**)&xn, g_xn);
    cudaGetSymbolAddress((void**)&xr, g_xr);
    cudaGetSymbolAddress((void**)&xs, g_xs);
    cudaGetSymbolAddress((void**)&xdbl, g_xdbl);
    cudaGetSymbolAddress((void**)&delta, g_delta);
    cudaGetSymbolAddress((void**)&yb, g_y);
    cudaGetSymbolAddress((void**)&wi, g_wi);
    cudaGetSymbolAddress((void**)&wo, g_wo);
    cudaGetSymbolAddress((void**)&wx, g_wx);
    cudaGetSymbolAddress((void**)&wdt, g_wdt);

    copy_kernel<<<(TOKENS * DMODEL / 4) / 256, 256>>>(x, hb, TOKENS * DMODEL / 4);

    for (int i = 0; i < 2; i++) {
        const float* Wi_l  = Wi + (size_t)i * (2 * DI) * DMODEL;
        const float* bi_l  = bi + (size_t)i * (2 * DI);
        const float* cw_l  = cw + (size_t)i * DI * 5;
        const float* cb_l  = cb + (size_t)i * DI;
        const float* Wx_l  = Wx + (size_t)i * XDBL_W * DI;
        const float* Wdt_l = Wdt + (size_t)i * DI * DTR;
        const float* bdt_l = bdt + (size_t)i * DI;
        const float* Al_l  = A_log + (size_t)i * DI * NSTATE;
        const float* D_l   = Dv + (size_t)i * DI;
        const float* Wo_l  = Wo + (size_t)i * DMODEL * DI;
        const float* bo_l  = bo + (size_t)i * DMODEL;
        const float* nw_l  = norm_w + (size_t)i * DMODEL;

        rmsnorm_kernel<<<TOKENS, 256>>>(hb, nw_l, xn, 1);

        round_tf32_kernel<<<((2 * DI) * DMODEL / 4) / 256, 256>>>(Wi_l, wi, (2 * DI) * DMODEL / 4);
        round_tf32_kernel<<<(DMODEL * DI / 4) / 256, 256>>>(Wo_l, wo, DMODEL * DI / 4);
        round_tf32_kernel<<<(XDBL_W * DI / 4 + 255) / 256, 256>>>(Wx_l, wx, XDBL_W * DI / 4);
        round_tf32_kernel<<<(DI * DTR / 4 + 255) / 256, 256>>>(Wdt_l, wdt, DI * DTR / 4);

        // xr = xn @ Wi^T + bi   [4096 x 4096], K=1024
        {
            dim3 g((2 * DI) / 128, TOKENS / 128);
            gemm_mma<0, 0><<<g, 256, GEMM_SMEM>>>(xn, DMODEL, wi, DMODEL, bi_l, xr, 2 * DI,
                                                  2 * DI, DMODEL);
        }

        conv_silu_kernel<<<(TOKENS * DI) / 256, 256>>>(xr, cw_l, cb_l, xs);

        // xdbl = xs @ Wx^T   [4096 x 96], K=2048 (tf32-rounded output)
        {
            dim3 g(1, TOKENS / 128);
            gemm_mma<0, 1><<<g, 256, GEMM_SMEM>>>(xs, DI, wx, DI, (const float*)0, xdbl, XDBL_W,
                                                  XDBL_W, DI);
        }

        // delta = softplus(xdbl[:, :64] @ Wdt^T + bdt)   [4096 x 2048], K=64
        {
            dim3 g(DI / 128, TOKENS / 128);
            gemm_mma<1, 0><<<g, 256, GEMM_SMEM>>>(xdbl, XDBL_W, wdt, DTR, bdt_l, delta, DI,
                                                  DI, DTR);
        }

        scan_kernel<<<(BATCH * DI * NSTATE) / 256, 256>>>(delta, xs, xdbl, Al_l, D_l, xr, yb);

        // h += y @ Wo^T + bo   [4096 x 1024], K=2048
        {
            dim3 g(DMODEL / 128, TOKENS / 128);
            gemm_mma<2, 0><<<g, 256, GEMM_SMEM>>>(yb, DI, wo, DI, bo_l, hb, DMODEL,
                                                  DMODEL, DI);
        }
    }

    rmsnorm_kernel<<<TOKENS, 256>>>(hb, nfw, out, 0);
}

// round 4
// speedup vs baseline: 2.0759x; 1.1682x over previous
#include <cuda_runtime.h>
#include <cuda_fp16.h>
#include <math.h>
#include <cstdint>

#define TOKENS 4096
#define BATCH  4
#define LSEQ   1024
#define DMODEL 1024
#define DI     2048
#define NSTATE 16
#define DTR    64
#define XDBL_W 96

// ---------------- helpers ----------------
__device__ __forceinline__ uint32_t smem_to_u32(const void* p) {
    uint32_t a;
    asm("{ .reg .u64 t; cvta.to.shared.u64 t, %1; cvt.u32.u64 %0, t; }" : "=r"(a) : "l"(p));
    return a;
}
__device__ __forceinline__ void cp16(uint32_t dst, const void* src, uint32_t nbytes) {
    asm volatile("cp.async.cg.shared.global [%0], [%1], 16, %2;"
                 :: "r"(dst), "l"(src), "r"(nbytes) : "memory");
}
__device__ __forceinline__ float softplusf(float x) {
    return (x > 20.0f) ? x : log1pf(__expf(x));
}
__device__ __forceinline__ float siluf(float x) { return x / (1.0f + __expf(-x)); }

#define MMA_F16(c, a, b) \
    asm volatile("mma.sync.aligned.m16n8k16.row.col.f32.f16.f16.f32 " \
        "{%0,%1,%2,%3}, {%4,%5,%6,%7}, {%8,%9}, {%0,%1,%2,%3};" \
        : "+f"((c)[0]), "+f"((c)[1]), "+f"((c)[2]), "+f"((c)[3]) \
        : "r"((a)[0]), "r"((a)[1]), "r"((a)[2]), "r"((a)[3]), \
          "r"((b)[0]), "r"((b)[1]))

// ---------------- scratch (device globals) ----------------
__device__ __align__(256) float  g_h[TOKENS * DMODEL];
__device__ __align__(256) float  g_xr[TOKENS * (2 * DI)];
__device__ __align__(256) float  g_xs[TOKENS * DI];
__device__ __align__(256) float  g_xdbl[TOKENS * XDBL_W];
__device__ __align__(256) float  g_delta[TOKENS * DI];
__device__ __align__(256) __half g_xn_h[TOKENS * DMODEL];
__device__ __align__(256) __half g_xs_h[TOKENS * DI];
__device__ __align__(256) __half g_xdbl_h[TOKENS * XDBL_W];
__device__ __align__(256) __half g_y_h[TOKENS * DI];
__device__ __align__(256) __half g_wi_h[2 * (2 * DI) * DMODEL];
__device__ __align__(256) __half g_wo_h[2 * DMODEL * DI];
__device__ __align__(256) __half g_wx_h[2 * XDBL_W * DI];
__device__ __align__(256) __half g_wdt_h[2 * DI * DTR];

// ---------------- elementwise kernels ----------------
__global__ void __launch_bounds__(256) f2h_kernel(const float* __restrict__ src,
                                                  __half* __restrict__ dst, int n4) {
    int i = blockIdx.x * 256 + threadIdx.x;
    if (i < n4) {
        float4 v = ((const float4*)src)[i];
        __half2 h0 = __floats2half2_rn(v.x, v.y);
        __half2 h1 = __floats2half2_rn(v.z, v.w);
        uint2 o;
        o.x = *(uint32_t*)&h0; o.y = *(uint32_t*)&h1;
        ((uint2*)dst)[i] = o;
    }
}

// MODE 0: src=x, write hb(fp32)+xn_h; MODE 1: write xn_h only; MODE 2: write fp32 out
template <int MODE>
__global__ void __launch_bounds__(256) rmsnorm_kernel(const float* __restrict__ src,
                                                      const float* __restrict__ w,
                                                      float* __restrict__ dst_f,
                                                      __half* __restrict__ dst_h) {
    int row = blockIdx.x;
    const float4* s = (const float4*)(src + (size_t)row * DMODEL);
    float4 v = s[threadIdx.x];
    float ss = v.x * v.x + v.y * v.y + v.z * v.z + v.w * v.w;
    #pragma unroll
    for (int o = 16; o; o >>= 1) ss += __shfl_xor_sync(0xffffffffu, ss, o);
    __shared__ float wsum[8];
    if ((threadIdx.x & 31) == 0) wsum[threadIdx.x >> 5] = ss;
    __syncthreads();
    float tot = 0.f;
    #pragma unroll
    for (int i = 0; i < 8; i++) tot += wsum[i];
    float rs = rsqrtf(tot * (1.0f / DMODEL) + 1e-5f);
    float4 wv = ((const float4*)w)[threadIdx.x];
    float4 o;
    o.x = v.x * rs * wv.x; o.y = v.y * rs * wv.y;
    o.z = v.z * rs * wv.z; o.w = v.w * rs * wv.w;
    if (MODE == 0)
        ((float4*)(dst_f + (size_t)row * DMODEL))[threadIdx.x] = v;  // hb = x
    if (MODE == 2) {
        ((float4*)(dst_f + (size_t)row * DMODEL))[threadIdx.x] = o;
    } else {
        __half2 h0 = __floats2half2_rn(o.x, o.y);
        __half2 h1 = __floats2half2_rn(o.z, o.w);
        uint2 u; u.x = *(uint32_t*)&h0; u.y = *(uint32_t*)&h1;
        ((uint2*)(dst_h + (size_t)row * DMODEL))[threadIdx.x] = u;
    }
}

__global__ void __launch_bounds__(256) conv_silu_kernel(
    const float* __restrict__ xr, const float* __restrict__ cw,
    const float* __restrict__ cb, float* __restrict__ xs,
    __half* __restrict__ xs_h) {
    int idx = blockIdx.x * 256 + threadIdx.x;
    int c = idx & (DI - 1);
    int tok = idx >> 11;
    int t = tok & (LSEQ - 1);
    int b = tok >> 10;
    const float* base = xr + (size_t)(b * LSEQ) * (2 * DI) + c;
    float acc = cb[c];
    #pragma unroll
    for (int j = 0; j < 5; j++) {
        int tt = t + j - 2;
        if (tt >= 0 && tt < LSEQ)
            acc = fmaf(base[(size_t)tt * (2 * DI)], __ldg(cw + c * 5 + j), acc);
    }
    float v = siluf(acc);
    xs[idx] = v;
    xs_h[idx] = __float2half_rn(v);
}

__global__ void __launch_bounds__(256) scan_kernel(
    const float* __restrict__ delta, const float* __restrict__ u,
    const float* __restrict__ xdbl, const float* __restrict__ A_log,
    const float* __restrict__ Dv, const float* __restrict__ xr,
    __half* __restrict__ y) {
    int gid = blockIdx.x * 256 + threadIdx.x;
    int n = gid & 15;
    int hw = gid >> 4;
    int d = hw & (DI - 1);
    int b = hw >> 11;
    float A = -__expf(A_log[d * NSTATE + n]);
    float Dd = Dv[d];
    float h = 0.f;
    const float* dptr = delta + (size_t)(b * LSEQ) * DI + d;
    const float* uptr = u + (size_t)(b * LSEQ) * DI + d;
    const float* xptr = xdbl + (size_t)(b * LSEQ) * XDBL_W;
    const float* rptr = xr + (size_t)(b * LSEQ) * (2 * DI) + DI + d;
    __half* yptr = y + (size_t)(b * LSEQ) * DI + d;
    #pragma unroll 4
    for (int t = 0; t < LSEQ; t++) {
        float dlt = dptr[(size_t)t * DI];
        float uu = uptr[(size_t)t * DI];
        float Bn = xptr[t * XDBL_W + DTR + n];
        float Cn = xptr[t * XDBL_W + DTR + NSTATE + n];
        float dA = __expf(dlt * A);
        h = fmaf(dA, h, dlt * uu * Bn);
        float v = h * Cn;
        v += __shfl_xor_sync(0xffffffffu, v, 8);
        v += __shfl_xor_sync(0xffffffffu, v, 4);
        v += __shfl_xor_sync(0xffffffffu, v, 2);
        v += __shfl_xor_sync(0xffffffffu, v, 1);
        if (n == 0) {
            float r = rptr[(size_t)t * (2 * DI)];
            yptr[(size_t)t * DI] = __float2half_rn((v + uu * Dd) * siluf(r));
        }
    }
}

// ---------------- fp16 mma.sync GEMM ----------------
// C[M,N] = A[M,K] @ B[N,K]^T (+ epilogue). BM=BN=128, BK=32, 8 warps (warp 64x32).
// EPI: 0 = (+bias), 1 = softplus(+bias), 2 = C += acc + bias
// WH: also write __half copy of C to C2
#define GBK 32
#define NSTG 4
#define HSTR 40                           // halfs per smem row (80B, conflict-free)
#define STAGE_HALFS (2 * 128 * HSTR)      // 10240 halfs
#define STAGE_BYTES (STAGE_HALFS * 2)     // 20480
#define GEMM_SMEM   (NSTG * STAGE_BYTES)  // 81920

template <int EPI, int WH>
__global__ void __launch_bounds__(256) gemm_mma(
    const __half* __restrict__ A, int lda,
    const __half* __restrict__ B, int ldb,
    const float* __restrict__ bias,
    float* __restrict__ C, __half* __restrict__ C2, int ldc,
    int N, int K) {
    extern __shared__ __half sm[];
    const uint32_t sbase = smem_to_u32(sm);
    const int tid = threadIdx.x;
    const int lane = tid & 31;
    const int wid = tid >> 5;
    const int wm = (wid >> 2) * 64;
    const int wn = (wid & 3) * 32;
    const int bm = blockIdx.y * 128;
    const int bn = blockIdx.x * 128;
    const int NK = K / GBK;

    const int row1 = tid >> 2;        // 0..63
    const int kp = tid & 3;           // 16B chunk (8 halfs)
    const uint32_t dA1 = row1 * (HSTR * 2) + kp * 16;
    const uint32_t dA2 = dA1 + 64 * (HSTR * 2);
    const uint32_t dB = 128 * HSTR * 2;

    const __half* aRow1 = A + (size_t)(bm + row1) * lda + kp * 8;
    const __half* aRow2 = aRow1 + (size_t)64 * lda;
    const int brow1 = bn + row1, brow2 = bn + row1 + 64;
    const uint32_t nb1 = (brow1 < N) ? 16u : 0u;
    const uint32_t nb2 = (brow2 < N) ? 16u : 0u;
    const __half* bRow1 = B + (size_t)(brow1 < N ? brow1 : 0) * ldb + kp * 8;
    const __half* bRow2 = B + (size_t)(brow2 < N ? brow2 : 0) * ldb + kp * 8;

    #pragma unroll
    for (int s = 0; s < NSTG - 1; s++) {
        if (s < NK) {
            uint32_t st = sbase + s * STAGE_BYTES;
            int k0 = s * GBK;
            cp16(st + dA1, aRow1 + k0, 16);
            cp16(st + dA2, aRow2 + k0, 16);
            cp16(st + dB + dA1, bRow1 + k0, nb1);
            cp16(st + dB + dA2, bRow2 + k0, nb2);
        }
        asm volatile("cp.async.commit_group;" ::: "memory");
    }

    float acc[4][4][4];
    #pragma unroll
    for (int mt = 0; mt < 4; mt++)
        #pragma unroll
        for (int nt = 0; nt < 4; nt++)
            #pragma unroll
            for (int r = 0; r < 4; r++) acc[mt][nt][r] = 0.f;

    const int fr = lane >> 2;   // g
    const int fc = lane & 3;    // tig

    for (int kt = 0; kt < NK; kt++) {
        asm volatile("cp.async.wait_group %0;" :: "n"(NSTG - 2));
        __syncthreads();

        if (kt + NSTG - 1 < NK) {
            uint32_t st = sbase + ((kt + NSTG - 1) & (NSTG - 1)) * STAGE_BYTES;
            int k0 = (kt + NSTG - 1) * GBK;
            cp16(st + dA1, aRow1 + k0, 16);
            cp16(st + dA2, aRow2 + k0, 16);
            cp16(st + dB + dA1, bRow1 + k0, nb1);
            cp16(st + dB + dA2, bRow2 + k0, nb2);
        }
        asm volatile("cp.async.commit_group;" ::: "memory");

        const __half* As = sm + (kt & (NSTG - 1)) * STAGE_HALFS;
        const __half* Bs = As + 128 * HSTR;

        #pragma unroll
        for (int ks = 0; ks < 2; ks++) {
            const int cb = ks * 16 + 2 * fc;
            uint32_t a[4][4], b[4][2];
            #pragma unroll
            for (int mt = 0; mt < 4; mt++) {
                const __half* ap = As + (wm + mt * 16 + fr) * HSTR + cb;
                a[mt][0] = *(const uint32_t*)ap;
                a[mt][1] = *(const uint32_t*)(ap + 8 * HSTR);
                a[mt][2] = *(const uint32_t*)(ap + 8);
                a[mt][3] = *(const uint32_t*)(ap + 8 * HSTR + 8);
            }
            #pragma unroll
            for (int nt = 0; nt < 4; nt++) {
                const __half* bp = Bs + (wn + nt * 8 + fr) * HSTR + cb;
                b[nt][0] = *(const uint32_t*)bp;
                b[nt][1] = *(const uint32_t*)(bp + 8);
            }
            #pragma unroll
            for (int mt = 0; mt < 4; mt++)
                #pragma unroll
                for (int nt = 0; nt < 4; nt++)
                    MMA_F16(acc[mt][nt], a[mt], b[nt]);
        }
        __syncthreads();
    }

    // epilogue
    #pragma unroll
    for (int mt = 0; mt < 4; mt++) {
        const int row = bm + wm + mt * 16 + fr;
        #pragma unroll
        for (int nt = 0; nt < 4; nt++) {
            const int col = bn + wn + nt * 8 + 2 * fc;
            if (col < N) {
                #pragma unroll
                for (int half = 0; half < 2; half++) {
                    const int r = row + half * 8;
                    float2 v;
                    v.x = acc[mt][nt][half * 2];
                    v.y = acc[mt][nt][half * 2 + 1];
                    if (bias) { v.x += bias[col]; v.y += bias[col + 1]; }
                    if (EPI == 1) { v.x = softplusf(v.x); v.y = softplusf(v.y); }
                    if (EPI == 2) {
                        float2 o = *(const float2*)(C + (size_t)r * ldc + col);
                        v.x += o.x; v.y += o.y;
                    }
                    *(float2*)(C + (size_t)r * ldc + col) = v;
                    if (WH) {
                        __half2 h = __floats2half2_rn(v.x, v.y);
                        *(uint32_t*)(C2 + (size_t)r * ldc + col) = *(uint32_t*)&h;
                    }
                }
            }
        }
    }
}

// ---------------- host ----------------
extern "C" void kernel_launch(void* const* d_in, const int* in_sizes, int n_in,
                              void* d_out, int out_size) {
    const float* x      = (const float*)d_in[0];
    const float* Wi     = (const float*)d_in[1];
    const float* bi     = (const float*)d_in[2];
    const float* cw     = (const float*)d_in[3];
    const float* cb     = (const float*)d_in[4];
    const float* Wx     = (const float*)d_in[5];
    const float* Wdt    = (const float*)d_in[6];
    const float* bdt    = (const float*)d_in[7];
    const float* A_log  = (const float*)d_in[8];
    const float* Dv     = (const float*)d_in[9];
    const float* Wo     = (const float*)d_in[10];
    const float* bo     = (const float*)d_in[11];
    const float* norm_w = (const float*)d_in[12];
    const float* nfw    = (const float*)d_in[13];
    float* out = (float*)d_out;

    cudaFuncSetAttribute(gemm_mma<0, 0>, cudaFuncAttributeMaxDynamicSharedMemorySize, GEMM_SMEM);
    cudaFuncSetAttribute(gemm_mma<0, 1>, cudaFuncAttributeMaxDynamicSharedMemorySize, GEMM_SMEM);
    cudaFuncSetAttribute(gemm_mma<1, 0>, cudaFuncAttributeMaxDynamicSharedMemorySize, GEMM_SMEM);
    cudaFuncSetAttribute(gemm_mma<2, 0>, cudaFuncAttributeMaxDynamicSharedMemorySize, GEMM_SMEM);

    float *hb, *xr, *xs, *xdbl, *delta;
    __half *xnh, *xsh, *xdh, *yh, *wih, *woh, *wxh, *wdth;
    cudaGetSymbolAddress((void**)&hb, g_h);
    cudaGetSymbolAddress((void**)&xr, g_xr);
    cudaGetSymbolAddress((void**)&xs, g_xs);
    cudaGetSymbolAddress((void**)&xdbl, g_xdbl);
    cudaGetSymbolAddress((void**)&delta, g_delta);
    cudaGetSymbolAddress((void**)&xnh, g_xn_h);
    cudaGetSymbolAddress((void**)&xsh, g_xs_h);
    cudaGetSymbolAddress((void**)&xdh, g_xdbl_h);
    cudaGetSymbolAddress((void**)&yh, g_y_h);
    cudaGetSymbolAddress((void**)&wih, g_wi_h);
    cudaGetSymbolAddress((void**)&woh, g_wo_h);
    cudaGetSymbolAddress((void**)&wxh, g_wx_h);
    cudaGetSymbolAddress((void**)&wdth, g_wdt_h);

    // weight conversion (both layers, hoisted) — launches 1-4
    f2h_kernel<<<(2 * (2 * DI) * DMODEL / 4) / 256, 256>>>(Wi, wih, 2 * (2 * DI) * DMODEL / 4);
    f2h_kernel<<<(2 * DMODEL * DI / 4) / 256, 256>>>(Wo, woh, 2 * DMODEL * DI / 4);
    f2h_kernel<<<(2 * XDBL_W * DI / 4 + 255) / 256, 256>>>(Wx, wxh, 2 * XDBL_W * DI / 4);
    f2h_kernel<<<(2 * DI * DTR / 4 + 255) / 256, 256>>>(Wdt, wdth, 2 * DI * DTR / 4);

    for (int i = 0; i < 2; i++) {
        const __half* wi_l  = wih + (size_t)i * (2 * DI) * DMODEL;
        const float*  bi_l  = bi + (size_t)i * (2 * DI);
        const float*  cw_l  = cw + (size_t)i * DI * 5;
        const float*  cb_l  = cb + (size_t)i * DI;
        const __half* wx_l  = wxh + (size_t)i * XDBL_W * DI;
        const __half* wdt_l = wdth + (size_t)i * DI * DTR;
        const float*  bdt_l = bdt + (size_t)i * DI;
        const float*  Al_l  = A_log + (size_t)i * DI * NSTATE;
        const float*  D_l   = Dv + (size_t)i * DI;
        const __half* wo_l  = woh + (size_t)i * DMODEL * DI;
        const float*  bo_l  = bo + (size_t)i * DMODEL;
        const float*  nw_l  = norm_w + (size_t)i * DMODEL;

        // launch 5 (layer 0): rmsnorm (+ h=x copy on layer 0)
        if (i == 0)
            rmsnorm_kernel<0><<<TOKENS, 256>>>(x, nw_l, hb, xnh);
        else
            rmsnorm_kernel<1><<<TOKENS, 256>>>(hb, nw_l, (float*)0, xnh);

        // launch 6 (layer 0): in_proj — profiled by ncu -s 5 -c 1
        {
            dim3 g((2 * DI) / 128, TOKENS / 128);
            gemm_mma<0, 0><<<g, 256, GEMM_SMEM>>>(xnh, DMODEL, wi_l, DMODEL, bi_l,
                                                  xr, (__half*)0, 2 * DI, 2 * DI, DMODEL);
        }

        conv_silu_kernel<<<(TOKENS * DI) / 256, 256>>>(xr, cw_l, cb_l, xs, xsh);

        // xdbl = xs @ Wx^T (fp32 + fp16 copies)
        {
            dim3 g(1, TOKENS / 128);
            gemm_mma<0, 1><<<g, 256, GEMM_SMEM>>>(xsh, DI, wx_l, DI, (const float*)0,
                                                  xdbl, xdh, XDBL_W, XDBL_W, DI);
        }

        // delta = softplus(xdbl[:, :64] @ Wdt^T + bdt)
        {
            dim3 g(DI / 128, TOKENS / 128);
            gemm_mma<1, 0><<<g, 256, GEMM_SMEM>>>(xdh, XDBL_W, wdt_l, DTR, bdt_l,
                                                  delta, (__half*)0, DI, DI, DTR);
        }

        scan_kernel<<<(BATCH * DI * NSTATE) / 256, 256>>>(delta, xs, xdbl, Al_l, D_l, xr, yh);

        // h += y @ Wo^T + bo
        {
            dim3 g(DMODEL / 128, TOKENS / 128);
            gemm_mma<2, 0><<<g, 256, GEMM_SMEM>>>(yh, DI, wo_l, DI, bo_l,
                                                  hb, (__half*)0, DMODEL, DMODEL, DI);
        }
    }

    rmsnorm_kernel<2><<<TOKENS, 256>>>(hb, nfw, out, (__half*)0);
}

// round 5
// speedup vs baseline: 2.1434x; 1.0325x over previous
#include <cuda_runtime.h>
#include <cuda_fp16.h>
#include <math.h>
#include <cstdint>

#define TOKENS 4096
#define BATCH  4
#define LSEQ   1024
#define DMODEL 1024
#define DI     2048
#define NSTATE 16
#define DTR    64
#define XDBL_W 96

// ---------------- helpers ----------------
__device__ __forceinline__ uint32_t smem_to_u32(const void* p) {
    uint32_t a;
    asm("{ .reg .u64 t; cvta.to.shared.u64 t, %1; cvt.u32.u64 %0, t; }" : "=r"(a) : "l"(p));
    return a;
}
__device__ __forceinline__ void cp16(uint32_t dst, const void* src, uint32_t nbytes) {
    asm volatile("cp.async.cg.shared.global [%0], [%1], 16, %2;"
                 :: "r"(dst), "l"(src), "r"(nbytes) : "memory");
}
__device__ __forceinline__ float softplusf(float x) {
    return (x > 20.0f) ? x : log1pf(__expf(x));
}
__device__ __forceinline__ float siluf(float x) { return x / (1.0f + __expf(-x)); }

#define MMA_F16(c, a, b) \
    asm volatile("mma.sync.aligned.m16n8k16.row.col.f32.f16.f16.f32 " \
        "{%0,%1,%2,%3}, {%4,%5,%6,%7}, {%8,%9}, {%0,%1,%2,%3};" \
        : "+f"((c)[0]), "+f"((c)[1]), "+f"((c)[2]), "+f"((c)[3]) \
        : "r"((a)[0]), "r"((a)[1]), "r"((a)[2]), "r"((a)[3]), \
          "r"((b)[0]), "r"((b)[1]))

#define LDSM_X4(r0, r1, r2, r3, addr) \
    asm volatile("ldmatrix.sync.aligned.m8n8.x4.shared.b16 {%0,%1,%2,%3}, [%4];" \
        : "=r"(r0), "=r"(r1), "=r"(r2), "=r"(r3) : "r"(addr))

// ---------------- scratch (device globals) ----------------
__device__ __align__(256) float  g_h[TOKENS * DMODEL];
__device__ __align__(256) float  g_xr[TOKENS * (2 * DI)];
__device__ __align__(256) float  g_xs[TOKENS * DI];
__device__ __align__(256) float  g_xdbl[TOKENS * XDBL_W];
__device__ __align__(256) float  g_delta[TOKENS * DI];
__device__ __align__(256) __half g_xn_h[TOKENS * DMODEL];
__device__ __align__(256) __half g_xs_h[TOKENS * DI];
__device__ __align__(256) __half g_xdbl_h[TOKENS * XDBL_W];
__device__ __align__(256) __half g_y_h[TOKENS * DI];
__device__ __align__(256) __half g_wi_h[2 * (2 * DI) * DMODEL];
__device__ __align__(256) __half g_wo_h[2 * DMODEL * DI];
__device__ __align__(256) __half g_wx_h[2 * XDBL_W * DI];
__device__ __align__(256) __half g_wdt_h[2 * DI * DTR];

// ---------------- elementwise kernels ----------------
__global__ void __launch_bounds__(256) f2h_kernel(const float* __restrict__ src,
                                                  __half* __restrict__ dst, int n4) {
    int i = blockIdx.x * 256 + threadIdx.x;
    if (i < n4) {
        float4 v = ((const float4*)src)[i];
        __half2 h0 = __floats2half2_rn(v.x, v.y);
        __half2 h1 = __floats2half2_rn(v.z, v.w);
        uint2 o;
        o.x = *(uint32_t*)&h0; o.y = *(uint32_t*)&h1;
        ((uint2*)dst)[i] = o;
    }
}

// MODE 0: src=x, write hb(fp32)+xn_h; MODE 1: write xn_h only; MODE 2: write fp32 out
template <int MODE>
__global__ void __launch_bounds__(256) rmsnorm_kernel(const float* __restrict__ src,
                                                      const float* __restrict__ w,
                                                      float* __restrict__ dst_f,
                                                      __half* __restrict__ dst_h) {
    int row = blockIdx.x;
    const float4* s = (const float4*)(src + (size_t)row * DMODEL);
    float4 v = s[threadIdx.x];
    float ss = v.x * v.x + v.y * v.y + v.z * v.z + v.w * v.w;
    #pragma unroll
    for (int o = 16; o; o >>= 1) ss += __shfl_xor_sync(0xffffffffu, ss, o);
    __shared__ float wsum[8];
    if ((threadIdx.x & 31) == 0) wsum[threadIdx.x >> 5] = ss;
    __syncthreads();
    float tot = 0.f;
    #pragma unroll
    for (int i = 0; i < 8; i++) tot += wsum[i];
    float rs = rsqrtf(tot * (1.0f / DMODEL) + 1e-5f);
    float4 wv = ((const float4*)w)[threadIdx.x];
    float4 o;
    o.x = v.x * rs * wv.x; o.y = v.y * rs * wv.y;
    o.z = v.z * rs * wv.z; o.w = v.w * rs * wv.w;
    if (MODE == 0)
        ((float4*)(dst_f + (size_t)row * DMODEL))[threadIdx.x] = v;  // hb = x
    if (MODE == 2) {
        ((float4*)(dst_f + (size_t)row * DMODEL))[threadIdx.x] = o;
    } else {
        __half2 h0 = __floats2half2_rn(o.x, o.y);
        __half2 h1 = __floats2half2_rn(o.z, o.w);
        uint2 u; u.x = *(uint32_t*)&h0; u.y = *(uint32_t*)&h1;
        ((uint2*)(dst_h + (size_t)row * DMODEL))[threadIdx.x] = u;
    }
}

__global__ void __launch_bounds__(256) conv_silu_kernel(
    const float* __restrict__ xr, const float* __restrict__ cw,
    const float* __restrict__ cb, float* __restrict__ xs,
    __half* __restrict__ xs_h) {
    int idx = blockIdx.x * 256 + threadIdx.x;
    int c = idx & (DI - 1);
    int tok = idx >> 11;
    int t = tok & (LSEQ - 1);
    int b = tok >> 10;
    const float* base = xr + (size_t)(b * LSEQ) * (2 * DI) + c;
    float acc = cb[c];
    #pragma unroll
    for (int j = 0; j < 5; j++) {
        int tt = t + j - 2;
        if (tt >= 0 && tt < LSEQ)
            acc = fmaf(base[(size_t)tt * (2 * DI)], __ldg(cw + c * 5 + j), acc);
    }
    float v = siluf(acc);
    xs[idx] = v;
    xs_h[idx] = __float2half_rn(v);
}

__global__ void __launch_bounds__(256) scan_kernel(
    const float* __restrict__ delta, const float* __restrict__ u,
    const float* __restrict__ xdbl, const float* __restrict__ A_log,
    const float* __restrict__ Dv, const float* __restrict__ xr,
    __half* __restrict__ y) {
    int gid = blockIdx.x * 256 + threadIdx.x;
    int n = gid & 15;
    int hw = gid >> 4;
    int d = hw & (DI - 1);
    int b = hw >> 11;
    float A = -__expf(A_log[d * NSTATE + n]);
    float Dd = Dv[d];
    float h = 0.f;
    const float* dptr = delta + (size_t)(b * LSEQ) * DI + d;
    const float* uptr = u + (size_t)(b * LSEQ) * DI + d;
    const float* xptr = xdbl + (size_t)(b * LSEQ) * XDBL_W;
    const float* rptr = xr + (size_t)(b * LSEQ) * (2 * DI) + DI + d;
    __half* yptr = y + (size_t)(b * LSEQ) * DI + d;
    #pragma unroll 4
    for (int t = 0; t < LSEQ; t++) {
        float dlt = dptr[(size_t)t * DI];
        float uu = uptr[(size_t)t * DI];
        float Bn = xptr[t * XDBL_W + DTR + n];
        float Cn = xptr[t * XDBL_W + DTR + NSTATE + n];
        float dA = __expf(dlt * A);
        h = fmaf(dA, h, dlt * uu * Bn);
        float v = h * Cn;
        v += __shfl_xor_sync(0xffffffffu, v, 8);
        v += __shfl_xor_sync(0xffffffffu, v, 4);
        v += __shfl_xor_sync(0xffffffffu, v, 2);
        v += __shfl_xor_sync(0xffffffffu, v, 1);
        if (n == 0) {
            float r = rptr[(size_t)t * (2 * DI)];
            yptr[(size_t)t * DI] = __float2half_rn((v + uu * Dd) * siluf(r));
        }
    }
}

// ---------------- fp16 mma.sync GEMM (ldmatrix + 2 CTAs/SM) ----------------
// C[M,N] = A[M,K] @ B[N,K]^T (+ epilogue). BM=BN=128, BK=32, 8 warps (warp 64x32).
#define GBK 32
#define NSTG 4
#define HSTR 40
#define STAGE_HALFS (2 * 128 * HSTR)
#define STAGE_BYTES (STAGE_HALFS * 2)
#define GEMM_SMEM   (NSTG * STAGE_BYTES)

template <int EPI, int WH>
__global__ void __launch_bounds__(256, 2) gemm_mma(
    const __half* __restrict__ A, int lda,
    const __half* __restrict__ B, int ldb,
    const float* __restrict__ bias,
    float* __restrict__ C, __half* __restrict__ C2, int ldc,
    int N, int K) {
    extern __shared__ __half sm[];
    const uint32_t sbase = smem_to_u32(sm);
    const int tid = threadIdx.x;
    const int lane = tid & 31;
    const int wid = tid >> 5;
    const int wm = (wid >> 2) * 64;
    const int wn = (wid & 3) * 32;
    const int bm = blockIdx.y * 128;
    const int bn = blockIdx.x * 128;
    const int NK = K / GBK;

    // ----- cp.async coords -----
    const int row1 = tid >> 2;        // 0..63
    const int kp = tid & 3;           // 16B chunk (8 halfs)
    const uint32_t dA1 = row1 * (HSTR * 2) + kp * 16;
    const uint32_t dA2 = dA1 + 64 * (HSTR * 2);
    const uint32_t dB = 128 * HSTR * 2;

    const __half* aRow1 = A + (size_t)(bm + row1) * lda + kp * 8;
    const __half* aRow2 = aRow1 + (size_t)64 * lda;
    const int brow1 = bn + row1, brow2 = bn + row1 + 64;
    const uint32_t nb1 = (brow1 < N) ? 16u : 0u;
    const uint32_t nb2 = (brow2 < N) ? 16u : 0u;
    const __half* bRow1 = B + (size_t)(brow1 < N ? brow1 : 0) * ldb + kp * 8;
    const __half* bRow2 = B + (size_t)(brow2 < N ? brow2 : 0) * ldb + kp * 8;

    // ----- ldmatrix per-lane offsets (bytes within stage) -----
    // A: mats {m0-7,k0-7},{m8-15,k0-7},{m0-7,k8-15},{m8-15,k8-15}
    const int a_row = (lane & 7) | ((lane >> 3) & 1) << 3;
    const uint32_t aoffL = (uint32_t)(wm + a_row) * (HSTR * 2) + ((lane >> 4) & 1) * 16;
    // B: mats {n0-7,k0-7},{n0-7,k8-15},{n8-15,k0-7},{n8-15,k8-15}
    const int b_row = (lane & 7) | ((lane >> 4) & 1) << 3;
    const uint32_t boffL = dB + (uint32_t)(wn + b_row) * (HSTR * 2) + ((lane >> 3) & 1) * 16;

    #pragma unroll
    for (int s = 0; s < NSTG - 1; s++) {
        if (s < NK) {
            uint32_t st = sbase + s * STAGE_BYTES;
            int k0 = s * GBK;
            cp16(st + dA1, aRow1 + k0, 16);
            cp16(st + dA2, aRow2 + k0, 16);
            cp16(st + dB + dA1, bRow1 + k0, nb1);
            cp16(st + dB + dA2, bRow2 + k0, nb2);
        }
        asm volatile("cp.async.commit_group;" ::: "memory");
    }

    float acc[4][4][4];
    #pragma unroll
    for (int mt = 0; mt < 4; mt++)
        #pragma unroll
        for (int nt = 0; nt < 4; nt++)
            #pragma unroll
            for (int r = 0; r < 4; r++) acc[mt][nt][r] = 0.f;

    for (int kt = 0; kt < NK; kt++) {
        asm volatile("cp.async.wait_group %0;" :: "n"(NSTG - 2));
        __syncthreads();

        if (kt + NSTG - 1 < NK) {
            uint32_t st = sbase + ((kt + NSTG - 1) & (NSTG - 1)) * STAGE_BYTES;
            int k0 = (kt + NSTG - 1) * GBK;
            cp16(st + dA1, aRow1 + k0, 16);
            cp16(st + dA2, aRow2 + k0, 16);
            cp16(st + dB + dA1, bRow1 + k0, nb1);
            cp16(st + dB + dA2, bRow2 + k0, nb2);
        }
        asm volatile("cp.async.commit_group;" ::: "memory");

        const uint32_t stage = sbase + (kt & (NSTG - 1)) * STAGE_BYTES;

        #pragma unroll
        for (int ks = 0; ks < 2; ks++) {
            const uint32_t kb = ks * 32;
            uint32_t a[4][4], b[4][2];
            #pragma unroll
            for (int mt = 0; mt < 4; mt++)
                LDSM_X4(a[mt][0], a[mt][1], a[mt][2], a[mt][3],
                        stage + aoffL + mt * (16 * HSTR * 2) + kb);
            #pragma unroll
            for (int np = 0; np < 2; np++)
                LDSM_X4(b[2 * np][0], b[2 * np][1], b[2 * np + 1][0], b[2 * np + 1][1],
                        stage + boffL + np * (16 * HSTR * 2) + kb);
            #pragma unroll
            for (int mt = 0; mt < 4; mt++)
                #pragma unroll
                for (int nt = 0; nt < 4; nt++)
                    MMA_F16(acc[mt][nt], a[mt], b[nt]);
        }
        __syncthreads();
    }

    // epilogue
    const int fr = lane >> 2;
    const int fc = lane & 3;
    #pragma unroll
    for (int mt = 0; mt < 4; mt++) {
        const int row = bm + wm + mt * 16 + fr;
        #pragma unroll
        for (int nt = 0; nt < 4; nt++) {
            const int col = bn + wn + nt * 8 + 2 * fc;
            if (col < N) {
                #pragma unroll
                for (int half = 0; half < 2; half++) {
                    const int r = row + half * 8;
                    float2 v;
                    v.x = acc[mt][nt][half * 2];
                    v.y = acc[mt][nt][half * 2 + 1];
                    if (bias) { v.x += bias[col]; v.y += bias[col + 1]; }
                    if (EPI == 1) { v.x = softplusf(v.x); v.y = softplusf(v.y); }
                    if (EPI == 2) {
                        float2 o = *(const float2*)(C + (size_t)r * ldc + col);
                        v.x += o.x; v.y += o.y;
                    }
                    *(float2*)(C + (size_t)r * ldc + col) = v;
                    if (WH) {
                        __half2 h = __floats2half2_rn(v.x, v.y);
                        *(uint32_t*)(C2 + (size_t)r * ldc + col) = *(uint32_t*)&h;
                    }
                }
            }
        }
    }
}

// ---------------- host ----------------
extern "C" void kernel_launch(void* const* d_in, const int* in_sizes, int n_in,
                              void* d_out, int out_size) {
    const float* x      = (const float*)d_in[0];
    const float* Wi     = (const float*)d_in[1];
    const float* bi     = (const float*)d_in[2];
    const float* cw     = (const float*)d_in[3];
    const float* cb     = (const float*)d_in[4];
    const float* Wx     = (const float*)d_in[5];
    const float* Wdt    = (const float*)d_in[6];
    const float* bdt    = (const float*)d_in[7];
    const float* A_log  = (const float*)d_in[8];
    const float* Dv     = (const float*)d_in[9];
    const float* Wo     = (const float*)d_in[10];
    const float* bo     = (const float*)d_in[11];
    const float* norm_w = (const float*)d_in[12];
    const float* nfw    = (const float*)d_in[13];
    float* out = (float*)d_out;

    cudaFuncSetAttribute(gemm_mma<0, 0>, cudaFuncAttributeMaxDynamicSharedMemorySize, GEMM_SMEM);
    cudaFuncSetAttribute(gemm_mma<0, 1>, cudaFuncAttributeMaxDynamicSharedMemorySize, GEMM_SMEM);
    cudaFuncSetAttribute(gemm_mma<1, 0>, cudaFuncAttributeMaxDynamicSharedMemorySize, GEMM_SMEM);
    cudaFuncSetAttribute(gemm_mma<2, 0>, cudaFuncAttributeMaxDynamicSharedMemorySize, GEMM_SMEM);

    float *hb, *xr, *xs, *xdbl, *delta;
    __half *xnh, *xsh, *xdh, *yh, *wih, *woh, *wxh, *wdth;
    cudaGetSymbolAddress((void**)&hb, g_h);
    cudaGetSymbolAddress((void**)&xr, g_xr);
    cudaGetSymbolAddress((void**)&xs, g_xs);
    cudaGetSymbolAddress((void**)&xdbl, g_xdbl);
    cudaGetSymbolAddress((void**)&delta, g_delta);
    cudaGetSymbolAddress((void**)&xnh, g_xn_h);
    cudaGetSymbolAddress((void**)&xsh, g_xs_h);
    cudaGetSymbolAddress((void**)&xdh, g_xdbl_h);
    cudaGetSymbolAddress((void**)&yh, g_y_h);
    cudaGetSymbolAddress((void**)&wih, g_wi_h);
    cudaGetSymbolAddress((void**)&woh, g_wo_h);
    cudaGetSymbolAddress((void**)&wxh, g_wx_h);
    cudaGetSymbolAddress((void**)&wdth, g_wdt_h);

    f2h_kernel<<<(2 * (2 * DI) * DMODEL / 4) / 256, 256>>>(Wi, wih, 2 * (2 * DI) * DMODEL / 4);
    f2h_kernel<<<(2 * DMODEL * DI / 4) / 256, 256>>>(Wo, woh, 2 * DMODEL * DI / 4);
    f2h_kernel<<<(2 * XDBL_W * DI / 4 + 255) / 256, 256>>>(Wx, wxh, 2 * XDBL_W * DI / 4);
    f2h_kernel<<<(2 * DI * DTR / 4 + 255) / 256, 256>>>(Wdt, wdth, 2 * DI * DTR / 4);

    for (int i = 0; i < 2; i++) {
        const __half* wi_l  = wih + (size_t)i * (2 * DI) * DMODEL;
        const float*  bi_l  = bi + (size_t)i * (2 * DI);
        const float*  cw_l  = cw + (size_t)i * DI * 5;
        const float*  cb_l  = cb + (size_t)i * DI;
        const __half* wx_l  = wxh + (size_t)i * XDBL_W * DI;
        const __half* wdt_l = wdth + (size_t)i * DI * DTR;
        const float*  bdt_l = bdt + (size_t)i * DI;
        const float*  Al_l  = A_log + (size_t)i * DI * NSTATE;
        const float*  D_l   = Dv + (size_t)i * DI;
        const __half* wo_l  = woh + (size_t)i * DMODEL * DI;
        const float*  bo_l  = bo + (size_t)i * DMODEL;
        const float*  nw_l  = norm_w + (size_t)i * DMODEL;

        if (i == 0)
            rmsnorm_kernel<0><<<TOKENS, 256>>>(x, nw_l, hb, xnh);
        else
            rmsnorm_kernel<1><<<TOKENS, 256>>>(hb, nw_l, (float*)0, xnh);

        {
            dim3 g((2 * DI) / 128, TOKENS / 128);
            gemm_mma<0, 0><<<g, 256, GEMM_SMEM>>>(xnh, DMODEL, wi_l, DMODEL, bi_l,
                                                  xr, (__half*)0, 2 * DI, 2 * DI, DMODEL);
        }

        conv_silu_kernel<<<(TOKENS * DI) / 256, 256>>>(xr, cw_l, cb_l, xs, xsh);

        {
            dim3 g(1, TOKENS / 128);
            gemm_mma<0, 1><<<g, 256, GEMM_SMEM>>>(xsh, DI, wx_l, DI, (const float*)0,
                                                  xdbl, xdh, XDBL_W, XDBL_W, DI);
        }

        {
            dim3 g(DI / 128, TOKENS / 128);
            gemm_mma<1, 0><<<g, 256, GEMM_SMEM>>>(xdh, XDBL_W, wdt_l, DTR, bdt_l,
                                                  delta, (__half*)0, DI, DI, DTR);
        }

        scan_kernel<<<(BATCH * DI * NSTATE) / 256, 256>>>(delta, xs, xdbl, Al_l, D_l, xr, yh);

        {
            dim3 g(DMODEL / 128, TOKENS / 128);
            gemm_mma<2, 0><<<g, 256, GEMM_SMEM>>>(yh, DI, wo_l, DI, bo_l,
                                                  hb, (__half*)0, DMODEL, DMODEL, DI);
        }
    }

    rmsnorm_kernel<2><<<TOKENS, 256>>>(hb, nfw, out, (__half*)0);
}